// round 17
// baseline (speedup 1.0000x reference)
#include <cuda_runtime.h>
#include <cuda_bf16.h>

// CSR multi-head SpMM: out[n,h,d] = sum_{e in row n} ew[e,h] * nf[col[e],h,d]
// N=50000, E=800000, H=8, D=8 -> 64 floats per row.
//
// R16 = R15 (28.7us: balanced tiles + smem weights + fused zero/fill +
// float2 RED flush) with TILE=64: same validated per-edge loop body, half
// the stage/sync cost per edge, half the blocks, ~10% fewer segment
// flushes. Wall analysis: working set (~45MB) is L2-resident during graph
// replay; spmm sits near the LTS roofline (~256MB @ ~11TB/s), so gains come
// from stage amortization + flush traffic + overhead, not loop slimming.

#define H 8
#define D 8
#define ROW_ELEMS (H * D)
#define TILE 64
#define WPB 4            // warps per block in spmm kernel
#define MAX_EDGES 800000

__device__ int g_dst[MAX_EDGES];

__global__ __launch_bounds__(256) void fill_dst_kernel(
    const int* __restrict__ row_ptr, float* __restrict__ out, int n_nodes)
{
    int warp = (blockIdx.x * blockDim.x + threadIdx.x) >> 5;
    int lane = threadIdx.x & 31;
    if (warp >= n_nodes) return;

    // zero this output row (accumulation target) - replaces memset node
    // 64 floats = 16 float4; lanes 0-15 each write one float4
    if (lane < 16) {
        float4 z; z.x = 0.f; z.y = 0.f; z.z = 0.f; z.w = 0.f;
        *reinterpret_cast<float4*>(out + (size_t)warp * ROW_ELEMS + lane * 4) = z;
    }

    int s = __ldg(&row_ptr[warp]);
    int e = __ldg(&row_ptr[warp + 1]);
    for (int j = s + lane; j < e; j += 32)
        g_dst[j] = warp;                    // coalesced, fire-and-forget
}

__global__ __launch_bounds__(32 * WPB) void spmm_balanced_kernel(
    const int* __restrict__ col_idx,
    const float* __restrict__ edge_weight,   // [E, 8]
    const float* __restrict__ node_feat,     // [N, 64]
    float* __restrict__ out,                 // [N, 64]
    int n_edges)
{
    __shared__ int   sdst[WPB][TILE];
    __shared__ int   scol[WPB][TILE];
    __shared__ float sweight[WPB][TILE * H];   // 2KB per warp tile

    int wip  = threadIdx.x >> 5;
    int lane = threadIdx.x & 31;
    int tile = blockIdx.x * WPB + wip;
    int base = tile * TILE;
    if (base >= n_edges) return;

    int h = lane >> 2;
    float ax = 0.0f, ay = 0.0f;

    if (base + TILE <= n_edges) {
        // stage cols + dsts (2 coalesced LDGs each) and weights (4 float4/lane)
        scol[wip][lane]      = __ldg(&col_idx[base + lane]);
        scol[wip][lane + 32] = __ldg(&col_idx[base + lane + 32]);
        sdst[wip][lane]      = __ldg(&g_dst[base + lane]);
        sdst[wip][lane + 32] = __ldg(&g_dst[base + lane + 32]);
        {
            const float4* wsrc = reinterpret_cast<const float4*>(
                edge_weight + (size_t)base * H);
            float4* wdst = reinterpret_cast<float4*>(sweight[wip]);
            #pragma unroll
            for (int k = 0; k < TILE * H / 4 / 32; ++k)    // 4 iterations
                wdst[lane + 32 * k] = __ldg(&wsrc[lane + 32 * k]);
        }
        __syncwarp();

        #pragma unroll 4
        for (int j = 0; j < TILE; ++j) {
            int c   = scol[wip][j];                       // LDS broadcast
            float w = sweight[wip][j * H + h];            // LDS, conflict-free
            float2 f = *reinterpret_cast<const float2*>(
                node_feat + (size_t)c * ROW_ELEMS + lane * 2);
            ax = fmaf(w, f.x, ax);
            ay = fmaf(w, f.y, ay);
            // warp-uniform flush at segment boundary / tile end
            if (j == TILE - 1 || sdst[wip][j + 1] != sdst[wip][j]) {
                float2 v; v.x = ax; v.y = ay;
                atomicAdd(reinterpret_cast<float2*>(
                    out + (size_t)sdst[wip][j] * ROW_ELEMS + lane * 2), v);
                ax = 0.0f; ay = 0.0f;
            }
        }
    } else {
        // tail tile (not hit when E % 64 == 0): scalar path, per-edge atomics
        int nb = n_edges - base;
        for (int j = 0; j < nb; ++j) {
            int c   = __ldg(&col_idx[base + j]);
            float w = __ldg(&edge_weight[(size_t)(base + j) * H + h]);
            float2 f = *reinterpret_cast<const float2*>(
                node_feat + (size_t)c * ROW_ELEMS + lane * 2);
            int drow = __ldg(&g_dst[base + j]);
            float2 v; v.x = w * f.x; v.y = w * f.y;
            atomicAdd(reinterpret_cast<float2*>(
                out + (size_t)drow * ROW_ELEMS + lane * 2), v);
        }
    }
}

extern "C" void kernel_launch(void* const* d_in, const int* in_sizes, int n_in,
                              void* d_out, int out_size)
{
    const int*   row_ptr     = (const int*)d_in[0];
    const int*   col_idx     = (const int*)d_in[1];
    const float* edge_weight = (const float*)d_in[2];
    const float* node_feat   = (const float*)d_in[3];
    float*       out         = (float*)d_out;

    int n_nodes = in_sizes[0] - 1;   // row_ptr has N+1 entries
    int n_edges = in_sizes[1];       // col_idx element count

    // k1: zero output rows + per-edge destination rows (warp per row)
    int b1 = (n_nodes * 32 + 255) / 256;
    fill_dst_kernel<<<b1, 256>>>(row_ptr, out, n_nodes);

    // k2: balanced edge-tile SpMM
    int tiles = (n_edges + TILE - 1) / TILE;
    int b2 = (tiles + WPB - 1) / WPB;
    spmm_balanced_kernel<<<b2, 32 * WPB>>>(col_idx, edge_weight,
                                           node_feat, out, n_edges);
}